// round 8
// baseline (speedup 1.0000x reference)
#include <cuda_runtime.h>
#include <cuda_fp16.h>
#include <stdint.h>

#define B_TOT   16384
#define N_IN    6
#define N_MF    5
#define N_FUZZ  30
#define N_RULES 2048
#define NSPLIT  32
#define RPS     (N_RULES / NSPLIT)   // 64 rules per split
#define TPB     128
#define EPB     256                  // batch elems per block (2 per thread, half2)
#define NGROUP  (B_TOT / EPB)        // 64
#define EPS_F   1e-12f
#define SQRT_LOG2E 1.2011224087864498f   // sqrt(log2(e))

// Rule record: 32B. a = {off0..off3}, b = {off4, off5, ow0_bits, ow1_bits}
struct Rule { uint4 a; uint4 b; };

__constant__ Rule c_rules[N_RULES];            // 64 KB exactly
__device__   Rule g_rulepack[N_RULES];         // staging for D2D copy

// Scratch (__device__ globals: no allocation allowed)
__device__ float4 g_partial[NSPLIT * B_TOT];   // {l1, d0, d1, pad}
__device__ int    g_cnt[NGROUP];               // zero-init; reset after use

// ---- packed f32x2 helpers ----
typedef unsigned long long u64;
static __device__ __forceinline__ u64 pack2(float lo, float hi) {
    u64 r; asm("mov.b64 %0, {%1, %2};" : "=l"(r) : "f"(lo), "f"(hi)); return r;
}
static __device__ __forceinline__ void unpack2(float& lo, float& hi, u64 v) {
    asm("mov.b64 {%0, %1}, %2;" : "=f"(lo), "=f"(hi) : "l"(v));
}
static __device__ __forceinline__ u64 add2(u64 a, u64 b) {
    u64 r; asm("add.rn.f32x2 %0, %1, %2;" : "=l"(r) : "l"(a), "l"(b)); return r;
}
static __device__ __forceinline__ u64 fma2(u64 a, u64 b, u64 c) {
    u64 r; asm("fma.rn.f32x2 %0, %1, %2, %3;" : "=l"(r) : "l"(a), "l"(b), "l"(c)); return r;
}
static __device__ __forceinline__ float ex2(float v) {
    float r; asm("ex2.approx.ftz.f32 %0, %1;" : "=f"(r) : "f"(v)); return r;
}

// ---------------------------------------------------------------------------
// Prep: build the 32B rule records (byte offsets pre-shifted by the 512B row
// stride of the SMEM fuzz table; out-weights pre-gathered).
// ---------------------------------------------------------------------------
__global__ void prep_kernel(const int* __restrict__ input_rules,
                            const int* __restrict__ output_rules,
                            const float* __restrict__ out_centers) {
    int r = blockIdx.x * blockDim.x + threadIdx.x;
    if (r >= N_RULES) return;
    const int* ir = input_rules + r * N_IN;
    float ow0 = out_centers[output_rules[r * 2 + 0]];
    float ow1 = out_centers[output_rules[r * 2 + 1]];
    Rule rr;
    rr.a = make_uint4((unsigned)ir[0] << 9, (unsigned)ir[1] << 9,
                      (unsigned)ir[2] << 9, (unsigned)ir[3] << 9);
    rr.b = make_uint4((unsigned)ir[4] << 9, (unsigned)ir[5] << 9,
                      __float_as_uint(ow0), __float_as_uint(ow1));
    g_rulepack[r] = rr;
}

// ---------------------------------------------------------------------------
// Main fused kernel.
//  - Fuzz table in SMEM as half2 {fuzz[b0], fuzz[b1]}, b1 = b0+128; one
//    LDS.32 gather serves 2 elems; bank = tid mod 32 -> conflict-free.
//  - Rule records come from __constant__ (LDC, constant port): the shared
//    crossbar now carries ONLY the 6 gather wavefronts per rule.
//  - Fuzzify: per Gaussian 1 FFMA + 1 FMUL + 1 ex2.approx via precomputed
//    {c*a, a}, a = sqrt(log2e)/s.
//  - NSPLIT=32 -> grid 2048 -> ~8 blocks/SM resident for latency hiding.
//  - Last-arriving split block per group finalizes (deterministic order).
// ---------------------------------------------------------------------------
__global__ __launch_bounds__(TPB) void anfis_main_kernel(
    const float* __restrict__ x,
    const float* __restrict__ mf_centers,
    const float* __restrict__ mf_scales,
    float* __restrict__ out)
{
    __shared__ __half2 s_fuzz[N_FUZZ * TPB];  // 15 KB
    __shared__ float2  s_cs[N_FUZZ];          // {c*a, a}
    __shared__ int     s_flag;

    const int tid   = threadIdx.x;
    const int grp   = blockIdx.x;
    const int split = blockIdx.y;
    const int rbase = split * RPS;
    const int b0    = grp * EPB + tid;
    const int b1    = b0 + TPB;

    // ---- membership-function constants ----
    if (tid < N_FUZZ) {
        float c = mf_centers[tid];
        float s = mf_scales[tid];
        float a = __fdividef(SQRT_LOG2E, s);
        s_cs[tid] = make_float2(c * a, a);
    }
    __syncthreads();

    // ---- fuzzify both batch elems: exp(-z^2) = ex2(-(x*a - c*a)^2) ----
    {
        float xa[N_IN], xb[N_IN];
        #pragma unroll
        for (int i = 0; i < N_IN; i++) {
            xa[i] = x[b0 * N_IN + i];
            xb[i] = x[b1 * N_IN + i];
        }
        #pragma unroll
        for (int i = 0; i < N_IN; i++) {
            #pragma unroll
            for (int j = 0; j < N_MF; j++) {
                float2 cs = s_cs[i * N_MF + j];      // LDS.64 broadcast
                float ta = fmaf(xa[i], cs.y, -cs.x);
                float tb = fmaf(xb[i], cs.y, -cs.x);
                s_fuzz[(i * N_MF + j) * TPB + tid] =
                    __floats2half2_rn(ex2(-ta * ta), ex2(-tb * tb));
            }
        }
    }
    __syncthreads();

    // ---- rule loop: 6 LDS.32 gathers per rule; broadcasts on const port ----
    const char* fb = reinterpret_cast<const char*>(s_fuzz) + tid * 4;
    u64 l1 = 0, d0 = 0, d1 = 0;

    #pragma unroll 4
    for (int k = 0; k < RPS; k++) {
        const uint4 pa = c_rules[rbase + k].a;   // LDC.128 (uniform)
        const uint4 pb = c_rules[rbase + k].b;   // LDC.128 (uniform)

        __half2 f0 = *reinterpret_cast<const __half2*>(fb + pa.x);
        __half2 f1 = *reinterpret_cast<const __half2*>(fb + pa.y);
        __half2 f2 = *reinterpret_cast<const __half2*>(fb + pa.z);
        __half2 f3 = *reinterpret_cast<const __half2*>(fb + pa.w);
        __half2 f4 = *reinterpret_cast<const __half2*>(fb + pb.x);
        __half2 f5 = *reinterpret_cast<const __half2*>(fb + pb.y);

        __half2 w = __hmin2(__hmin2(__hmin2(f0, f1), __hmin2(f2, f3)),
                            __hmin2(f4, f5));

        u64 wp  = pack2(__low2float(w), __high2float(w));
        u64 ow0 = pack2(__uint_as_float(pb.z), __uint_as_float(pb.z));
        u64 ow1 = pack2(__uint_as_float(pb.w), __uint_as_float(pb.w));
        l1 = add2(l1, wp);              // weights >= 0
        d0 = fma2(wp, ow0, d0);
        d1 = fma2(wp, ow1, d1);
    }

    // ---- write partials ----
    {
        float la, lb, d0a, d0b, d1a, d1b;
        unpack2(la, lb, l1); unpack2(d0a, d0b, d0); unpack2(d1a, d1b, d1);
        g_partial[split * B_TOT + b0] = make_float4(la, d0a, d1a, 0.f);
        g_partial[split * B_TOT + b1] = make_float4(lb, d0b, d1b, 0.f);
    }

    // ---- last-block finalize (deterministic fixed-order summation) ----
    __threadfence();
    __syncthreads();
    if (tid == 0) {
        int old = atomicAdd(&g_cnt[grp], 1);
        s_flag = (old == NSPLIT - 1);
    }
    __syncthreads();

    if (s_flag) {
        __threadfence();
        #pragma unroll
        for (int e = 0; e < 2; e++) {
            const int b = (e == 0) ? b0 : b1;
            float l = 0.f, s0 = 0.f, s1 = 0.f;
            #pragma unroll
            for (int s = 0; s < NSPLIT; s++) {
                float4 p = __ldcg(&g_partial[s * B_TOT + b]);
                l += p.x; s0 += p.y; s1 += p.z;
            }
            float inv = __fdividef(1.0f, fmaxf(l, EPS_F));
            float o0 = tanhf(s0 * inv) * 4.0f;            // scale 4.0, center 0.0
            float o1 = tanhf(s1 * inv) * 0.75f + 0.75f;   // scale .75, center .75
            reinterpret_cast<float2*>(out)[b] = make_float2(o0, o1);
        }
        if (tid == 0) g_cnt[grp] = 0;   // reset for next graph replay
    }
}

// ---------------------------------------------------------------------------
extern "C" void kernel_launch(void* const* d_in, const int* in_sizes, int n_in,
                              void* d_out, int out_size) {
    const float* x            = (const float*)d_in[0];
    const float* mf_centers   = (const float*)d_in[1];
    const float* mf_scales    = (const float*)d_in[2];
    const float* out_centers  = (const float*)d_in[3];
    const int*   input_rules  = (const int*)d_in[4];
    const int*   output_rules = (const int*)d_in[5];

    prep_kernel<<<N_RULES / 256, 256>>>(input_rules, output_rules, out_centers);

    // Resolve both symbols to real device pointers (host-side query, no
    // allocation, capture-safe), then D2D memcpy into the constant bank.
    // (R7 bug: passing the __device__ symbol token as a host src pointer.)
    void *dst = nullptr, *src = nullptr;
    cudaGetSymbolAddress(&dst, c_rules);
    cudaGetSymbolAddress(&src, g_rulepack);
    cudaMemcpyAsync(dst, src, sizeof(Rule) * N_RULES,
                    cudaMemcpyDeviceToDevice, 0);

    dim3 grid(NGROUP, NSPLIT);
    anfis_main_kernel<<<grid, TPB>>>(x, mf_centers, mf_scales, (float*)d_out);
}